// round 5
// baseline (speedup 1.0000x reference)
#include <cuda_runtime.h>
#include <cuda_fp16.h>
#include <cstdint>

// Conv2d 3x3 s1 p1 (N=32, Cin=128, Cout=256, 56x56, fp32) via implicit GEMM,
// fp16 mma.sync single-pass. Round 5: BM=256 (full Cout, halves im2col traffic
// per output), BK=64, software-pipelined B gather (LDG -> MMA -> STS),
// warp tile 64x64, occ 1.

#define IN_C   128
#define OUT_C  256
#define HW     56
#define SP     3136
#define NKDIM  1152
#define NSPAT  100352
#define XPH    58
#define XPW    58
#define XPC    (XPH * XPW)       // 3364

#define BM 256
#define BN 128
#define BK 64
#define NCH (NKDIM / BK)         // 18
#define THREADS 256

#define A_STRIDE 144             // 64 fp16 = 128B + 16B pad
#define B_STRIDE 272             // 128 fp16 = 256B + 16B pad
#define A_BYTES  (256 * A_STRIDE)            // 36864
#define B_BYTES  (64 * B_STRIDE)             // 17408
#define BUF_BYTES (A_BYTES + B_BYTES)        // 54272
#define SMEM_TOTAL (2 * BUF_BYTES)           // 108544

__device__ __align__(16) __half g_wh[OUT_C * NKDIM];
__device__ __align__(16) __half g_xh[32 * IN_C * XPC];

#define LDSM4(r, addr) \
    asm volatile("ldmatrix.sync.aligned.m8n8.x4.shared.b16 {%0,%1,%2,%3}, [%4];" \
        : "=r"((r)[0]), "=r"((r)[1]), "=r"((r)[2]), "=r"((r)[3]) : "r"(addr))

#define LDSM4T(r0, r1, r2, r3, addr) \
    asm volatile("ldmatrix.sync.aligned.m8n8.x4.trans.shared.b16 {%0,%1,%2,%3}, [%4];" \
        : "=r"(r0), "=r"(r1), "=r"(r2), "=r"(r3) : "r"(addr))

#define MMA(d, a, b) \
    asm volatile("mma.sync.aligned.m16n8k16.row.col.f32.f16.f16.f32 " \
        "{%0,%1,%2,%3}, {%4,%5,%6,%7}, {%8,%9}, {%0,%1,%2,%3};" \
        : "+f"((d)[0]), "+f"((d)[1]), "+f"((d)[2]), "+f"((d)[3]) \
        : "r"((a)[0]), "r"((a)[1]), "r"((a)[2]), "r"((a)[3]), \
          "r"((b)[0]), "r"((b)[1]))

#define CP_ASYNC16(dst, src) \
    asm volatile("cp.async.cg.shared.global [%0], [%1], 16;" \
        :: "r"(dst), "l"(src) : "memory")
#define CP_COMMIT()  asm volatile("cp.async.commit_group;" ::: "memory")
#define CP_WAIT0()   asm volatile("cp.async.wait_group 0;" ::: "memory")

// ---------------- prepass: fp32 -> fp16 ----------------

__global__ void conv_w_kernel(const float* __restrict__ w) {
    int i = blockIdx.x * blockDim.x + threadIdx.x;
    if (i < OUT_C * NKDIM) g_wh[i] = __float2half(w[i]);
}

__global__ void conv_x_kernel(const float* __restrict__ x) {
    int i = blockIdx.x * blockDim.x + threadIdx.x;
    if (i >= 32 * IN_C * XPC) return;
    int iw = i % XPW;
    int t  = i / XPW;
    int ih = t % XPH;
    int c  = t / XPH;
    float v = 0.0f;
    if (ih >= 1 && ih <= HW && iw >= 1 && iw <= HW)
        v = x[c * SP + (ih - 1) * HW + (iw - 1)];
    g_xh[i] = __float2half(v);
}

// ---------------- helpers ----------------

__device__ __forceinline__ void stage_a(uint32_t sbuf, int k0, int tid) {
    // A: 256 rows x 64 fp16 (128B) = 2048 x 16B, 8 cp.async per thread
    #pragma unroll
    for (int g = 0; g < 8; g++) {
        int idx = tid + 256 * g;            // 0..2047
        int m   = idx >> 3;                 // 0..255
        int c8  = idx & 7;                  // 16B chunk in row
        const char* src = (const char*)(g_wh + m * NKDIM + k0) + c8 * 16;
        CP_ASYNC16(sbuf + m * A_STRIDE + c8 * 16, src);
    }
    CP_COMMIT();
}

__device__ __forceinline__ void gather_b(uint32_t bp[4][4], int ch,
                                         int cbase, int krow0) {
    // load this thread's 4 k-rows x 8 pixels for chunk ch into registers
    const unsigned short* xh = (const unsigned short*)g_xh;
    const int k0 = ch * BK;
    #pragma unroll
    for (int kk = 0; kk < 4; kk++) {
        int krow = krow0 + kk * 16;         // 0..63
        int kg = k0 + krow;
        int ic = kg / 9;
        int r  = kg - ic * 9;
        int kh = r / 3;
        int kw = r - kh * 3;
        int base = cbase + ic * XPC + kh * XPW + kw;
        #pragma unroll
        for (int j = 0; j < 4; j++)
            bp[kk][j] = (uint32_t)xh[base + 2*j]
                      | ((uint32_t)xh[base + 2*j + 1] << 16);
    }
}

__device__ __forceinline__ void store_b(uint32_t sbuf, const uint32_t bp[4][4],
                                        int krow0, int ngrp) {
    #pragma unroll
    for (int kk = 0; kk < 4; kk++) {
        uint32_t dst = sbuf + A_BYTES + (krow0 + kk * 16) * B_STRIDE + ngrp * 16;
        asm volatile("st.shared.v4.b32 [%0], {%1,%2,%3,%4};"
                     :: "r"(dst), "r"(bp[kk][0]), "r"(bp[kk][1]),
                        "r"(bp[kk][2]), "r"(bp[kk][3]) : "memory");
    }
}

// ---------------- main GEMM kernel ----------------

__global__ __launch_bounds__(THREADS, 1)
void conv_mma_kernel(const float* __restrict__ bias, float* __restrict__ out)
{
    extern __shared__ char smc[];
    const int tid = threadIdx.x;
    const int lid = tid & 31;
    const int wid = tid >> 5;
    const int bn0 = blockIdx.x * BN;
    const int wm0 = (wid >> 1) * 64;        // 4 warp rows
    const int wn0 = (wid & 1) * 64;         // 2 warp cols

    const int ngrp = tid & 15;              // n-group of 8 pixels
    const int krow0 = tid >> 4;             // 0..15
    int cbase;
    {
        int n0 = bn0 + ngrp * 8;
        int b  = n0 / SP;
        int s  = n0 - b * SP;
        int oh = s / HW;
        int ow0 = s - oh * HW;               // multiple of 8
        cbase = (b * IN_C) * XPC + oh * XPW + ow0;
    }

    const uint32_t sb = (uint32_t)__cvta_generic_to_shared(smc);

    float acc[4][8][4];
    #pragma unroll
    for (int mt = 0; mt < 4; mt++)
        #pragma unroll
        for (int nt = 0; nt < 8; nt++)
            #pragma unroll
            for (int q = 0; q < 4; q++)
                acc[mt][nt][q] = 0.0f;

    // prologue: stage chunk 0 into buf 0
    {
        uint32_t bp[4][4];
        gather_b(bp, 0, cbase, krow0);
        stage_a(sb, 0, tid);
        store_b(sb, bp, krow0, ngrp);
        CP_WAIT0();
        __syncthreads();
    }

    int buf = 0;
    #pragma unroll 1
    for (int ch = 0; ch < NCH; ch++) {
        const uint32_t cur = sb + buf * BUF_BYTES;
        const uint32_t nxt = sb + (buf ^ 1) * BUF_BYTES;
        const bool has_next = (ch + 1 < NCH);

        // issue next chunk's loads early (latency hidden under MMAs)
        uint32_t bp[4][4];
        if (has_next) {
            gather_b(bp, ch + 1, cbase, krow0);
            stage_a(nxt, (ch + 1) * BK, tid);
        }

        // compute current chunk: 4 k-steps x (4x8) MMAs
        #pragma unroll
        for (int ks = 0; ks < 4; ks++) {
            uint32_t afr[4][4], bfr[8][2];
            const uint32_t aoff = (uint32_t)((wm0 + (lid & 15)) * A_STRIDE
                                             + ks * 32 + (lid >> 4) * 16);
            #pragma unroll
            for (int mt = 0; mt < 4; mt++)
                LDSM4(afr[mt], cur + aoff + mt * 16 * A_STRIDE);

            const uint32_t boff = (uint32_t)(
                (ks * 16 + (lid & 7) + ((lid >> 3) & 1) * 8) * B_STRIDE
                + (wn0 + (lid >> 4) * 8) * 2) + cur + A_BYTES;
            #pragma unroll
            for (int g = 0; g < 4; g++)
                LDSM4T(bfr[2*g][0], bfr[2*g][1], bfr[2*g+1][0], bfr[2*g+1][1],
                       boff + g * 32);

            #pragma unroll
            for (int mt = 0; mt < 4; mt++)
                #pragma unroll
                for (int nt = 0; nt < 8; nt++)
                    MMA(acc[mt][nt], afr[mt], bfr[nt]);
        }

        if (has_next) {
            store_b(nxt, bp, krow0, ngrp);
            CP_WAIT0();
        }
        __syncthreads();
        buf ^= 1;
    }

    // epilogue: c-fragment direct stores (8B pairs)
    #pragma unroll
    for (int mt = 0; mt < 4; mt++) {
        int oc0 = wm0 + mt * 16 + (lid >> 2);
        float bv0 = __ldg(&bias[oc0]);
        float bv1 = __ldg(&bias[oc0 + 8]);
        #pragma unroll
        for (int nt = 0; nt < 8; nt++) {
            int n = bn0 + wn0 + nt * 8 + 2 * (lid & 3);
            int b = n / SP;
            int s = n - b * SP;
            float2 v0 = make_float2(acc[mt][nt][0] + bv0, acc[mt][nt][1] + bv0);
            float2 v1 = make_float2(acc[mt][nt][2] + bv1, acc[mt][nt][3] + bv1);
            *(float2*)&out[(b * OUT_C + oc0) * SP + s] = v0;
            *(float2*)&out[(b * OUT_C + oc0 + 8) * SP + s] = v1;
        }
    }
}

extern "C" void kernel_launch(void* const* d_in, const int* in_sizes, int n_in,
                              void* d_out, int out_size)
{
    const float* x    = (const float*)d_in[0];
    const float* w    = (const float*)d_in[1];
    const float* bias = (const float*)d_in[2];
    float* out        = (float*)d_out;

    int wtot = OUT_C * NKDIM;
    conv_w_kernel<<<(wtot + 255) / 256, 256>>>(w);
    int xtot = 32 * IN_C * XPC;
    conv_x_kernel<<<(xtot + 255) / 256, 256>>>(x);

    cudaFuncSetAttribute(conv_mma_kernel,
                         cudaFuncAttributeMaxDynamicSharedMemorySize, SMEM_TOTAL);
    dim3 grid(NSPAT / BN, 1);               // 784 CTAs
    conv_mma_kernel<<<grid, THREADS, SMEM_TOTAL>>>(bias, out);
}

// round 6
// speedup vs baseline: 1.1431x; 1.1431x over previous
#include <cuda_runtime.h>
#include <cuda_fp16.h>
#include <cstdint>

// Conv2d 3x3 s1 p1 (N=32, Cin=128, Cout=256, 56x56, fp32) via implicit GEMM,
// fp16 mma.sync single-pass. Round 6: back to BM=128/occ-2 skeleton (R4) +
// BK=64 (half the barriers) + register-pipelined B gather interleaved with
// the MMA k-steps. Prepass fused into one kernel (also fixes ncu capture).

#define IN_C   128
#define OUT_C  256
#define HW     56
#define SP     3136
#define NKDIM  1152
#define NSPAT  100352
#define XPH    58
#define XPW    58
#define XPC    (XPH * XPW)       // 3364
#define XTOT   (32 * IN_C * XPC)
#define WTOT   (OUT_C * NKDIM)

#define BM 128
#define BN 128
#define BK 64
#define NCH (NKDIM / BK)         // 18
#define THREADS 256

#define A_STRIDE 144             // 64 fp16 = 128B + 16B pad
#define B_STRIDE 272             // 128 fp16 = 256B + 16B pad
#define A_BYTES  (128 * A_STRIDE)            // 18432
#define B_BYTES  (64 * B_STRIDE)             // 17408
#define BUF_BYTES (A_BYTES + B_BYTES)        // 35840
#define SMEM_TOTAL (2 * BUF_BYTES)           // 71680

__device__ __align__(16) __half g_wh[WTOT];
__device__ __align__(16) __half g_xh[XTOT];

#define LDSM4(r, addr) \
    asm volatile("ldmatrix.sync.aligned.m8n8.x4.shared.b16 {%0,%1,%2,%3}, [%4];" \
        : "=r"((r)[0]), "=r"((r)[1]), "=r"((r)[2]), "=r"((r)[3]) : "r"(addr))

#define LDSM4T(r0, r1, r2, r3, addr) \
    asm volatile("ldmatrix.sync.aligned.m8n8.x4.trans.shared.b16 {%0,%1,%2,%3}, [%4];" \
        : "=r"(r0), "=r"(r1), "=r"(r2), "=r"(r3) : "r"(addr))

#define MMA(d, a, b) \
    asm volatile("mma.sync.aligned.m16n8k16.row.col.f32.f16.f16.f32 " \
        "{%0,%1,%2,%3}, {%4,%5,%6,%7}, {%8,%9}, {%0,%1,%2,%3};" \
        : "+f"((d)[0]), "+f"((d)[1]), "+f"((d)[2]), "+f"((d)[3]) \
        : "r"((a)[0]), "r"((a)[1]), "r"((a)[2]), "r"((a)[3]), \
          "r"((b)[0]), "r"((b)[1]))

#define CP_ASYNC16(dst, src) \
    asm volatile("cp.async.cg.shared.global [%0], [%1], 16;" \
        :: "r"(dst), "l"(src) : "memory")
#define CP_COMMIT()  asm volatile("cp.async.commit_group;" ::: "memory")
#define CP_WAIT0()   asm volatile("cp.async.wait_group 0;" ::: "memory")

// ---------------- fused prepass: fp32 -> fp16 (w, then padded x) ----------------

#define WBLKS ((WTOT + 255) / 256)
#define XBLKS ((XTOT + 255) / 256)

__global__ void conv_prep_kernel(const float* __restrict__ w,
                                 const float* __restrict__ x)
{
    int blk = blockIdx.x;
    if (blk < WBLKS) {
        int i = blk * 256 + threadIdx.x;
        if (i < WTOT) g_wh[i] = __float2half(w[i]);
    } else {
        int i = (blk - WBLKS) * 256 + threadIdx.x;
        if (i >= XTOT) return;
        int iw = i % XPW;
        int t  = i / XPW;
        int ih = t % XPH;
        int c  = t / XPH;
        float v = 0.0f;
        if (ih >= 1 && ih <= HW && iw >= 1 && iw <= HW)
            v = x[c * SP + (ih - 1) * HW + (iw - 1)];
        g_xh[i] = __float2half(v);
    }
}

// ---------------- helpers ----------------

__device__ __forceinline__ void stage_a(uint32_t sbuf, int k0, int tid, int bm0) {
    // A: 128 rows x 128B = 1024 x 16B, 4 cp.async per thread
    #pragma unroll
    for (int g = 0; g < 4; g++) {
        int idx = tid + 256 * g;            // 0..1023
        int m   = idx >> 3;                 // 0..127
        int c8  = idx & 7;
        const char* src = (const char*)(g_wh + (bm0 + m) * NKDIM + k0) + c8 * 16;
        CP_ASYNC16(sbuf + m * A_STRIDE + c8 * 16, src);
    }
    CP_COMMIT();
}

__device__ __forceinline__ void gather_half(uint32_t bp[2][4], int k0,
                                            int cbase, int krow0, int half) {
    const unsigned short* xh = (const unsigned short*)g_xh;
    #pragma unroll
    for (int kk = 0; kk < 2; kk++) {
        int krow = krow0 + kk * 16 + half * 32;   // 0..63
        int kg = k0 + krow;
        int ic = kg / 9;
        int r  = kg - ic * 9;
        int kh = r / 3;
        int kw = r - kh * 3;
        int base = cbase + ic * XPC + kh * XPW + kw;
        #pragma unroll
        for (int j = 0; j < 4; j++)
            bp[kk][j] = (uint32_t)xh[base + 2*j]
                      | ((uint32_t)xh[base + 2*j + 1] << 16);
    }
}

__device__ __forceinline__ void store_half(uint32_t sbuf, const uint32_t bp[2][4],
                                           int krow0, int ngrp, int half) {
    #pragma unroll
    for (int kk = 0; kk < 2; kk++) {
        uint32_t dst = sbuf + A_BYTES
                     + (krow0 + kk * 16 + half * 32) * B_STRIDE + ngrp * 16;
        asm volatile("st.shared.v4.b32 [%0], {%1,%2,%3,%4};"
                     :: "r"(dst), "r"(bp[kk][0]), "r"(bp[kk][1]),
                        "r"(bp[kk][2]), "r"(bp[kk][3]) : "memory");
    }
}

__device__ __forceinline__ void kstep(uint32_t cur, int ks, int wm0, int wn0,
                                      int lid, float acc[4][4][4]) {
    uint32_t afr[4][4], bfr[4][2];
    const uint32_t aoff = (uint32_t)((wm0 + (lid & 15)) * A_STRIDE
                                     + ks * 32 + (lid >> 4) * 16);
    #pragma unroll
    for (int mt = 0; mt < 4; mt++)
        LDSM4(afr[mt], cur + aoff + mt * 16 * A_STRIDE);

    const uint32_t boff = cur + A_BYTES + (uint32_t)(
        (ks * 16 + (lid & 7) + ((lid >> 3) & 1) * 8) * B_STRIDE
        + (wn0 + (lid >> 4) * 8) * 2);
    LDSM4T(bfr[0][0], bfr[0][1], bfr[1][0], bfr[1][1], boff);
    LDSM4T(bfr[2][0], bfr[2][1], bfr[3][0], bfr[3][1], boff + 32);

    #pragma unroll
    for (int mt = 0; mt < 4; mt++)
        #pragma unroll
        for (int nt = 0; nt < 4; nt++)
            MMA(acc[mt][nt], afr[mt], bfr[nt]);
}

// ---------------- main GEMM kernel ----------------

__global__ __launch_bounds__(THREADS, 2)
void conv_mma_kernel(const float* __restrict__ bias, float* __restrict__ out)
{
    extern __shared__ char smc[];
    const int tid = threadIdx.x;
    const int lid = tid & 31;
    const int wid = tid >> 5;
    const int bn0 = blockIdx.x * BN;
    const int bm0 = blockIdx.y * BM;
    const int wm0 = (wid >> 2) * 64;        // 2 warp rows
    const int wn0 = (wid & 3) * 32;         // 4 warp cols

    const int ngrp = tid & 15;
    const int krow0 = tid >> 4;             // 0..15
    int cbase;
    {
        int n0 = bn0 + ngrp * 8;
        int b  = n0 / SP;
        int s  = n0 - b * SP;
        int oh = s / HW;
        int ow0 = s - oh * HW;
        cbase = (b * IN_C) * XPC + oh * XPW + ow0;
    }

    const uint32_t sb = (uint32_t)__cvta_generic_to_shared(smc);

    float acc[4][4][4];
    #pragma unroll
    for (int mt = 0; mt < 4; mt++)
        #pragma unroll
        for (int nt = 0; nt < 4; nt++)
            #pragma unroll
            for (int q = 0; q < 4; q++)
                acc[mt][nt][q] = 0.0f;

    // prologue: stage chunk 0 into buf 0
    {
        uint32_t bp[2][4];
        stage_a(sb, 0, tid, bm0);
        gather_half(bp, 0, cbase, krow0, 0);
        store_half(sb, bp, krow0, ngrp, 0);
        gather_half(bp, 0, cbase, krow0, 1);
        store_half(sb, bp, krow0, ngrp, 1);
        CP_WAIT0();
        __syncthreads();
    }

    int buf = 0;
    #pragma unroll 1
    for (int ch = 0; ch < NCH; ch++) {
        const uint32_t cur = sb + buf * BUF_BYTES;
        const uint32_t nxt = sb + (buf ^ 1) * BUF_BYTES;
        const bool has_next = (ch + 1 < NCH);
        const int k1 = (ch + 1) * BK;

        uint32_t bp[2][4];
        if (has_next) {
            stage_a(nxt, k1, tid, bm0);
            gather_half(bp, k1, cbase, krow0, 0);   // LDGs in flight
        }

        kstep(cur, 0, wm0, wn0, lid, acc);
        kstep(cur, 1, wm0, wn0, lid, acc);

        if (has_next) {
            store_half(nxt, bp, krow0, ngrp, 0);
            gather_half(bp, k1, cbase, krow0, 1);
        }

        kstep(cur, 2, wm0, wn0, lid, acc);
        kstep(cur, 3, wm0, wn0, lid, acc);

        if (has_next) {
            store_half(nxt, bp, krow0, ngrp, 1);
            CP_WAIT0();
        }
        __syncthreads();
        buf ^= 1;
    }

    // epilogue: c-fragment direct stores (8B pairs)
    #pragma unroll
    for (int nt = 0; nt < 4; nt++) {
        int n = bn0 + wn0 + nt * 8 + 2 * (lid & 3);
        int b = n / SP;
        int s = n - b * SP;
        #pragma unroll
        for (int mt = 0; mt < 4; mt++) {
            int oc0 = bm0 + wm0 + mt * 16 + (lid >> 2);
            float bv0 = __ldg(&bias[oc0]);
            float bv1 = __ldg(&bias[oc0 + 8]);
            float2 v0 = make_float2(acc[mt][nt][0] + bv0, acc[mt][nt][1] + bv0);
            float2 v1 = make_float2(acc[mt][nt][2] + bv1, acc[mt][nt][3] + bv1);
            *(float2*)&out[(b * OUT_C + oc0) * SP + s] = v0;
            *(float2*)&out[(b * OUT_C + oc0 + 8) * SP + s] = v1;
        }
    }
}

extern "C" void kernel_launch(void* const* d_in, const int* in_sizes, int n_in,
                              void* d_out, int out_size)
{
    const float* x    = (const float*)d_in[0];
    const float* w    = (const float*)d_in[1];
    const float* bias = (const float*)d_in[2];
    float* out        = (float*)d_out;

    conv_prep_kernel<<<WBLKS + XBLKS, 256>>>(w, x);

    cudaFuncSetAttribute(conv_mma_kernel,
                         cudaFuncAttributeMaxDynamicSharedMemorySize, SMEM_TOTAL);
    dim3 grid(NSPAT / BN, OUT_C / BM);      // 784 x 2
    conv_mma_kernel<<<grid, THREADS, SMEM_TOTAL>>>(bias, out);
}

// round 7
// speedup vs baseline: 1.3109x; 1.1468x over previous
#include <cuda_runtime.h>
#include <cuda_fp16.h>
#include <cstdint>

// Conv2d 3x3 s1 p1 (N=32, Cin=128, Cout=256, 56x56, fp32) via implicit GEMM,
// fp16 mma.sync single-pass. Round 7: XPW=64 padded image + vectorized
// funnel-shift B gather (kills the scalar-LDG L1 hotspot), vectorized prepass.

#define IN_C   128
#define OUT_C  256
#define HW     56
#define SP     3136
#define NKDIM  1152
#define NSPAT  100352
#define XPH    58
#define XPW    64
#define XPC    (XPH * XPW)       // 3712
#define XTOT   (32 * IN_C * XPC)
#define WTOT   (OUT_C * NKDIM)

#define BM 128
#define BN 128
#define BK 64
#define NCH (NKDIM / BK)         // 18
#define THREADS 256

#define A_STRIDE 144             // 64 fp16 = 128B + 16B pad
#define B_STRIDE 272             // 128 fp16 = 256B + 16B pad
#define A_BYTES  (128 * A_STRIDE)            // 18432
#define B_BYTES  (64 * B_STRIDE)             // 17408
#define BUF_BYTES (A_BYTES + B_BYTES)        // 35840
#define SMEM_TOTAL (2 * BUF_BYTES)           // 71680

__device__ __align__(16) __half g_wh[WTOT];
__device__ __align__(16) __half g_xh[XTOT + 32];

#define LDSM4(r, addr) \
    asm volatile("ldmatrix.sync.aligned.m8n8.x4.shared.b16 {%0,%1,%2,%3}, [%4];" \
        : "=r"((r)[0]), "=r"((r)[1]), "=r"((r)[2]), "=r"((r)[3]) : "r"(addr))

#define LDSM4T(r0, r1, r2, r3, addr) \
    asm volatile("ldmatrix.sync.aligned.m8n8.x4.trans.shared.b16 {%0,%1,%2,%3}, [%4];" \
        : "=r"(r0), "=r"(r1), "=r"(r2), "=r"(r3) : "r"(addr))

#define MMA(d, a, b) \
    asm volatile("mma.sync.aligned.m16n8k16.row.col.f32.f16.f16.f32 " \
        "{%0,%1,%2,%3}, {%4,%5,%6,%7}, {%8,%9}, {%0,%1,%2,%3};" \
        : "+f"((d)[0]), "+f"((d)[1]), "+f"((d)[2]), "+f"((d)[3]) \
        : "r"((a)[0]), "r"((a)[1]), "r"((a)[2]), "r"((a)[3]), \
          "r"((b)[0]), "r"((b)[1]))

#define CP_ASYNC16(dst, src) \
    asm volatile("cp.async.cg.shared.global [%0], [%1], 16;" \
        :: "r"(dst), "l"(src) : "memory")
#define CP_COMMIT()  asm volatile("cp.async.commit_group;" ::: "memory")
#define CP_WAIT0()   asm volatile("cp.async.wait_group 0;" ::: "memory")

// ---------------- fused vectorized prepass ----------------
// w: 4 elems/thread (float4 -> 4 halves). x: 8 elems/thread -> one 16B store.

#define WBLKS (WTOT / 1024)              // 288
#define XSEGS (XTOT / 8)                 // 1900544
#define XBLKS (XSEGS / 256)              // 7424

__global__ void conv_prep_kernel(const float* __restrict__ w,
                                 const float* __restrict__ x)
{
    int blk = blockIdx.x;
    if (blk < WBLKS) {
        int i = (blk * 256 + threadIdx.x) * 4;
        float4 v = *reinterpret_cast<const float4*>(w + i);
        uint32_t p0 = (uint32_t)__half_as_ushort(__float2half(v.x))
                    | ((uint32_t)__half_as_ushort(__float2half(v.y)) << 16);
        uint32_t p1 = (uint32_t)__half_as_ushort(__float2half(v.z))
                    | ((uint32_t)__half_as_ushort(__float2half(v.w)) << 16);
        *reinterpret_cast<uint2*>(g_wh + i) = make_uint2(p0, p1);
    } else {
        int seg = (blk - WBLKS) * 256 + threadIdx.x;     // 0..XSEGS-1
        int iw0   = (seg & 7) * 8;
        int rowid = seg >> 3;                            // c*58 + ih
        int ih = rowid % XPH;
        int c  = rowid / XPH;
        const float* src = x + c * SP + (ih - 1) * HW + (iw0 - 1);
        bool ihok = (ih >= 1 && ih <= HW);
        uint32_t o[4];
        #pragma unroll
        for (int q = 0; q < 4; q++) {
            uint16_t h[2];
            #pragma unroll
            for (int e = 0; e < 2; e++) {
                int j  = q * 2 + e;
                int iw = iw0 + j;
                float v = (ihok && iw >= 1 && iw <= HW) ? src[j] : 0.0f;
                h[e] = __half_as_ushort(__float2half(v));
            }
            o[q] = (uint32_t)h[0] | ((uint32_t)h[1] << 16);
        }
        *reinterpret_cast<uint4*>(g_xh + rowid * XPW + iw0)
            = make_uint4(o[0], o[1], o[2], o[3]);
    }
}

// ---------------- helpers ----------------

__device__ __forceinline__ void stage_a(uint32_t sbuf, int k0, int tid, int bm0) {
    #pragma unroll
    for (int g = 0; g < 4; g++) {
        int idx = tid + 256 * g;            // 0..1023
        int m   = idx >> 3;                 // 0..127
        int c8  = idx & 7;
        const char* src = (const char*)(g_wh + (bm0 + m) * NKDIM + k0) + c8 * 16;
        CP_ASYNC16(sbuf + m * A_STRIDE + c8 * 16, src);
    }
    CP_COMMIT();
}

// vectorized im2col gather: base is 8-elem aligned + kw (kw in {0,1,2},
// warp-uniform per krow). One uint4 + uint2 load, funnel-shift extract.
__device__ __forceinline__ void gather_half(uint32_t bp[2][4], int k0,
                                            int cbase, int krow0, int half) {
    #pragma unroll
    for (int kk = 0; kk < 2; kk++) {
        int krow = krow0 + kk * 16 + half * 32;   // 0..63
        int kg = k0 + krow;
        int ic = kg / 9;
        int r  = kg - ic * 9;
        int kh = r / 3;
        int kw = r - kh * 3;
        int base = cbase + ic * XPC + kh * XPW;    // multiple of 8 elems
        uint4 v0 = *reinterpret_cast<const uint4*>(g_xh + base);
        uint2 v1 = *reinterpret_cast<const uint2*>(g_xh + base + 8);
        uint32_t w0 = v0.x, w1 = v0.y, w2 = v0.z, w3 = v0.w, w4 = v1.x, w5 = v1.y;
        if (kw == 2) { w0 = w1; w1 = w2; w2 = w3; w3 = w4; w4 = w5; }
        uint32_t sh = (kw & 1) ? 16u : 0u;
        bp[kk][0] = __funnelshift_r(w0, w1, sh);
        bp[kk][1] = __funnelshift_r(w1, w2, sh);
        bp[kk][2] = __funnelshift_r(w2, w3, sh);
        bp[kk][3] = __funnelshift_r(w3, w4, sh);
    }
}

__device__ __forceinline__ void store_half(uint32_t sbuf, const uint32_t bp[2][4],
                                           int krow0, int ngrp, int half) {
    #pragma unroll
    for (int kk = 0; kk < 2; kk++) {
        uint32_t dst = sbuf + A_BYTES
                     + (krow0 + kk * 16 + half * 32) * B_STRIDE + ngrp * 16;
        asm volatile("st.shared.v4.b32 [%0], {%1,%2,%3,%4};"
                     :: "r"(dst), "r"(bp[kk][0]), "r"(bp[kk][1]),
                        "r"(bp[kk][2]), "r"(bp[kk][3]) : "memory");
    }
}

__device__ __forceinline__ void kstep(uint32_t cur, int ks, int wm0, int wn0,
                                      int lid, float acc[4][4][4]) {
    uint32_t afr[4][4], bfr[4][2];
    const uint32_t aoff = (uint32_t)((wm0 + (lid & 15)) * A_STRIDE
                                     + ks * 32 + (lid >> 4) * 16);
    #pragma unroll
    for (int mt = 0; mt < 4; mt++)
        LDSM4(afr[mt], cur + aoff + mt * 16 * A_STRIDE);

    const uint32_t boff = cur + A_BYTES + (uint32_t)(
        (ks * 16 + (lid & 7) + ((lid >> 3) & 1) * 8) * B_STRIDE
        + (wn0 + (lid >> 4) * 8) * 2);
    LDSM4T(bfr[0][0], bfr[0][1], bfr[1][0], bfr[1][1], boff);
    LDSM4T(bfr[2][0], bfr[2][1], bfr[3][0], bfr[3][1], boff + 32);

    #pragma unroll
    for (int mt = 0; mt < 4; mt++)
        #pragma unroll
        for (int nt = 0; nt < 4; nt++)
            MMA(acc[mt][nt], afr[mt], bfr[nt]);
}

// ---------------- main GEMM kernel ----------------

__global__ __launch_bounds__(THREADS, 2)
void conv_mma_kernel(const float* __restrict__ bias, float* __restrict__ out)
{
    extern __shared__ char smc[];
    const int tid = threadIdx.x;
    const int lid = tid & 31;
    const int wid = tid >> 5;
    const int bn0 = blockIdx.x * BN;
    const int bm0 = blockIdx.y * BM;
    const int wm0 = (wid >> 2) * 64;
    const int wn0 = (wid & 3) * 32;

    const int ngrp = tid & 15;
    const int krow0 = tid >> 4;             // 0..15
    int cbase;
    {
        int n0 = bn0 + ngrp * 8;
        int b  = n0 / SP;
        int s  = n0 - b * SP;
        int oh = s / HW;
        int ow0 = s - oh * HW;               // multiple of 8
        cbase = (b * IN_C) * XPC + oh * XPW + ow0;   // multiple of 8
    }

    const uint32_t sb = (uint32_t)__cvta_generic_to_shared(smc);

    float acc[4][4][4];
    #pragma unroll
    for (int mt = 0; mt < 4; mt++)
        #pragma unroll
        for (int nt = 0; nt < 4; nt++)
            #pragma unroll
            for (int q = 0; q < 4; q++)
                acc[mt][nt][q] = 0.0f;

    // prologue
    {
        uint32_t bp[2][4];
        stage_a(sb, 0, tid, bm0);
        gather_half(bp, 0, cbase, krow0, 0);
        store_half(sb, bp, krow0, ngrp, 0);
        gather_half(bp, 0, cbase, krow0, 1);
        store_half(sb, bp, krow0, ngrp, 1);
        CP_WAIT0();
        __syncthreads();
    }

    int buf = 0;
    #pragma unroll 1
    for (int ch = 0; ch < NCH; ch++) {
        const uint32_t cur = sb + buf * BUF_BYTES;
        const uint32_t nxt = sb + (buf ^ 1) * BUF_BYTES;
        const bool has_next = (ch + 1 < NCH);
        const int k1 = (ch + 1) * BK;

        uint32_t bp[2][4];
        if (has_next) {
            stage_a(nxt, k1, tid, bm0);
            gather_half(bp, k1, cbase, krow0, 0);
        }

        kstep(cur, 0, wm0, wn0, lid, acc);
        kstep(cur, 1, wm0, wn0, lid, acc);

        if (has_next) {
            store_half(nxt, bp, krow0, ngrp, 0);
            gather_half(bp, k1, cbase, krow0, 1);
        }

        kstep(cur, 2, wm0, wn0, lid, acc);
        kstep(cur, 3, wm0, wn0, lid, acc);

        if (has_next) {
            store_half(nxt, bp, krow0, ngrp, 1);
            CP_WAIT0();
        }
        __syncthreads();
        buf ^= 1;
    }

    // epilogue
    #pragma unroll
    for (int nt = 0; nt < 4; nt++) {
        int n = bn0 + wn0 + nt * 8 + 2 * (lid & 3);
        int b = n / SP;
        int s = n - b * SP;
        #pragma unroll
        for (int mt = 0; mt < 4; mt++) {
            int oc0 = bm0 + wm0 + mt * 16 + (lid >> 2);
            float bv0 = __ldg(&bias[oc0]);
            float bv1 = __ldg(&bias[oc0 + 8]);
            float2 v0 = make_float2(acc[mt][nt][0] + bv0, acc[mt][nt][1] + bv0);
            float2 v1 = make_float2(acc[mt][nt][2] + bv1, acc[mt][nt][3] + bv1);
            *(float2*)&out[(b * OUT_C + oc0) * SP + s] = v0;
            *(float2*)&out[(b * OUT_C + oc0 + 8) * SP + s] = v1;
        }
    }
}

extern "C" void kernel_launch(void* const* d_in, const int* in_sizes, int n_in,
                              void* d_out, int out_size)
{
    const float* x    = (const float*)d_in[0];
    const float* w    = (const float*)d_in[1];
    const float* bias = (const float*)d_in[2];
    float* out        = (float*)d_out;

    conv_prep_kernel<<<WBLKS + XBLKS, 256>>>(w, x);

    cudaFuncSetAttribute(conv_mma_kernel,
                         cudaFuncAttributeMaxDynamicSharedMemorySize, SMEM_TOTAL);
    dim3 grid(NSPAT / BN, OUT_C / BM);      // 784 x 2
    conv_mma_kernel<<<grid, THREADS, SMEM_TOTAL>>>(bias, out);
}